// round 4
// baseline (speedup 1.0000x reference)
#include <cuda_runtime.h>
#include <math.h>

#define B      8
#define DIM    64
#define HEADS  2
#define CH     32
#define HH     256
#define WW     256
#define NPIX   65536
#define QKVC   192

typedef unsigned long long u64;
__device__ __forceinline__ void fma2(u64& d, u64 a, u64 b, u64 c) {
    asm("fma.rn.f32x2 %0,%1,%2,%3;" : "=l"(d) : "l"(a), "l"(b), "l"(c));
}
__device__ __forceinline__ u64 pk2(float lo, float hi) {
    u64 r; asm("mov.b64 %0,{%1,%2};" : "=l"(r) : "f"(lo), "f"(hi)); return r;
}
__device__ __forceinline__ float2 upk2(u64 v) {
    float2 r; asm("mov.b64 {%0,%1},%2;" : "=f"(r.x), "=f"(r.y) : "l"(v)); return r;
}

__device__ float g_mid[(size_t)B * QKVC * NPIX];
__device__ float g_v[(size_t)B * DIM * NPIX];       // v after depthwise conv
__device__ float g_gram[B * HEADS * CH * CH];
__device__ float g_sqn[B * 2 * DIM];
__device__ float g_A[B * HEADS * CH * CH];
__device__ float g_M[B * DIM * DIM];

__global__ void k_zero() {
    int t = blockIdx.x * blockDim.x + threadIdx.x;
    if (t < B * HEADS * CH * CH) g_gram[t] = 0.f;
    if (t < B * 2 * DIM)         g_sqn[t]  = 0.f;
}

// ---- kernel 1: 1x1 conv (unchanged from r2; f32x2, 12 oc x 8 px / thread) --
__global__ __launch_bounds__(256) void k_conv1(const float* __restrict__ x,
                                               const float* __restrict__ wqkv) {
    extern __shared__ float sm[];
    float* ws = sm;              // [64][192]
    float* xs = sm + 64 * QKVC;  // [64][128]
    const int b  = blockIdx.y;
    const long n0 = (long)blockIdx.x * 128;
    const int tx = threadIdx.x, ty = threadIdx.y;
    const int tid = ty * 16 + tx;

    for (int idx = tid; idx < QKVC * 64; idx += 256) {
        int oc = idx >> 6, k = idx & 63;
        ws[k * QKVC + oc] = wqkv[idx];
    }
    const float* xb = x + (size_t)b * DIM * NPIX + n0;
    for (int idx = tid; idx < 64 * 32; idx += 256) {
        int ic = idx >> 5, pv = idx & 31;
        ((float4*)&xs[ic * 128])[pv] = ((const float4*)(xb + (size_t)ic * NPIX))[pv];
    }
    __syncthreads();

    u64 acc[6][8];
#pragma unroll
    for (int p = 0; p < 6; p++)
#pragma unroll
        for (int j = 0; j < 8; j++) acc[p][j] = 0ull;

    const int ocb = ty * 12;
#pragma unroll 4
    for (int k = 0; k < 64; k++) {
        const ulonglong2* wp = (const ulonglong2*)(ws + k * QKVC + ocb);
        ulonglong2 wA = wp[0], wB = wp[1], wC = wp[2];
        u64 wr[6] = {wA.x, wA.y, wB.x, wB.y, wC.x, wC.y};
        u64 xd[8];
#pragma unroll
        for (int j = 0; j < 8; j++) {
            float xv = xs[k * 128 + tx + 16 * j];
            xd[j] = pk2(xv, xv);
        }
#pragma unroll
        for (int p = 0; p < 6; p++)
#pragma unroll
            for (int j = 0; j < 8; j++)
                fma2(acc[p][j], wr[p], xd[j], acc[p][j]);
    }

    float* ob = g_mid + (size_t)b * QKVC * NPIX + n0;
#pragma unroll
    for (int p = 0; p < 6; p++)
#pragma unroll
        for (int j = 0; j < 8; j++) {
            float2 r = upk2(acc[p][j]);
            ob[(size_t)(ocb + 2 * p) * NPIX + tx + 16 * j]     = r.x;
            ob[(size_t)(ocb + 2 * p + 1) * NPIX + tx + 16 * j] = r.y;
        }
}

// ---- kernel 2: fused dw(q,k) + sqn + Gram. One block = (b,h) x 32x8 tile ---
// smem: mids[64][340] (10x34 halo tile per ch) + qk_s[64][260]
__global__ __launch_bounds__(256) void k_dwgram(const float* __restrict__ wdw) {
    extern __shared__ float sm[];
    float* mids = sm;            // 64*340 = 21760
    float* qk_s = sm + 64 * 340; // 64*260 = 16640

    const int bh = blockIdx.z;
    const int b = bh >> 1, h = bh & 1;
    const int x0 = blockIdx.x * 32, y0 = blockIdx.y * 8;
    const int tid = threadIdx.x;

    // load 64 channel planes (q: ch 0..31 -> global h*32+ch, k: 32..63 -> 64+h*32+ch-32)
    const float* baseq = g_mid + ((size_t)b * QKVC + h * CH) * NPIX;
    const float* basek = g_mid + ((size_t)b * QKVC + DIM + h * CH) * NPIX;
    for (int idx = tid; idx < 64 * 340; idx += 256) {
        int ch = idx / 340, rem = idx - ch * 340;
        int yy = rem / 34, xx = rem - yy * 34;
        int gy = y0 + yy - 1, gx = x0 + xx - 1;
        const float* pl = (ch < 32) ? baseq + (size_t)ch * NPIX
                                    : basek + (size_t)(ch - 32) * NPIX;
        mids[idx] = (gy >= 0 && gy < HH && gx >= 0 && gx < WW)
                        ? pl[gy * WW + gx] : 0.f;
    }
    __syncthreads();

    // dw: thread -> (c = tid>>2, quarter pq = tid&3 -> rows 2pq..2pq+1)
    {
        const int c = tid >> 2, pq = tid & 3;
        const int gc = (c < 32) ? h * CH + c : DIM + h * CH + (c - 32);
        float w[9];
#pragma unroll
        for (int t = 0; t < 9; t++) w[t] = wdw[gc * 9 + t];
        float sq = 0.f;
#pragma unroll
        for (int rr = 0; rr < 2; rr++) {
            const int ly = 2 * pq + rr;
            for (int xx = 0; xx < 32; xx++) {
                float a = 0.f;
#pragma unroll
                for (int ky = 0; ky < 3; ky++)
#pragma unroll
                    for (int kx = 0; kx < 3; kx++)
                        a = fmaf(w[ky * 3 + kx], mids[c * 340 + (ly + ky) * 34 + xx + kx], a);
                qk_s[c * 260 + ly * 32 + xx] = a;
                sq = fmaf(a, a, sq);
            }
        }
        sq += __shfl_xor_sync(0xffffffffu, sq, 1);
        sq += __shfl_xor_sync(0xffffffffu, sq, 2);
        if (pq == 0) {
            int si = (c < 32) ? b * 2 * DIM + h * CH + c
                              : b * 2 * DIM + DIM + h * CH + (c - 32);
            atomicAdd(&g_sqn[si], sq);
        }
    }
    __syncthreads();

    // gram: 4 groups x (8x8); thread (gi,gj) owns rows {gi+8a} x {gj+8b}, px window 64g..64g+63
    const int g  = tid >> 6;
    const int gi = (tid >> 3) & 7;
    const int gj = tid & 7;
    u64 acc[4][4];
#pragma unroll
    for (int a = 0; a < 4; a++)
#pragma unroll
        for (int bb = 0; bb < 4; bb++) acc[a][bb] = 0ull;

#pragma unroll 4
    for (int p = g * 64; p < g * 64 + 64; p += 4) {
        ulonglong2 qa[4], kb[4];
#pragma unroll
        for (int a = 0; a < 4; a++) qa[a] = *(ulonglong2*)&qk_s[(gi + 8 * a) * 260 + p];
#pragma unroll
        for (int bb = 0; bb < 4; bb++) kb[bb] = *(ulonglong2*)&qk_s[(32 + gj + 8 * bb) * 260 + p];
#pragma unroll
        for (int a = 0; a < 4; a++)
#pragma unroll
            for (int bb = 0; bb < 4; bb++) {
                fma2(acc[a][bb], qa[a].x, kb[bb].x, acc[a][bb]);
                fma2(acc[a][bb], qa[a].y, kb[bb].y, acc[a][bb]);
            }
    }
    __syncthreads();
    float* red = mids;  // reuse as 4*1024 scratch
#pragma unroll
    for (int a = 0; a < 4; a++)
#pragma unroll
        for (int bb = 0; bb < 4; bb++) {
            float2 r = upk2(acc[a][bb]);
            red[g * 1024 + (gi + 8 * a) * 32 + gj + 8 * bb] = r.x + r.y;
        }
    __syncthreads();
    for (int t = tid; t < 1024; t += 256) {
        float s = red[t] + red[1024 + t] + red[2048 + t] + red[3072 + t];
        atomicAdd(&g_gram[bh * 1024 + t], s);
    }
}

// ---- kernel 3: depthwise conv for v channels only --------------------------
__global__ void k_dwv(const float* __restrict__ wdw) {
    const int bz = blockIdx.z;
    const int cl = bz & 63;          // 0..63
    const int b  = bz >> 6;
    const int c  = 128 + cl;         // global channel
    const int x0 = blockIdx.x * 32, y0 = blockIdx.y * 16;

    __shared__ float tile[18][34];
    const float* in = g_mid + ((size_t)b * QKVC + c) * NPIX;
    const int tid = threadIdx.y * 32 + threadIdx.x;

    for (int idx = tid; idx < 612; idx += 256) {
        int yy = idx / 34, xx = idx % 34;
        int gy = y0 + yy - 1, gx = x0 + xx - 1;
        tile[yy][xx] = (gy >= 0 && gy < HH && gx >= 0 && gx < WW)
                           ? in[gy * WW + gx] : 0.f;
    }
    __syncthreads();

    float w[9];
#pragma unroll
    for (int t = 0; t < 9; t++) w[t] = wdw[c * 9 + t];

    float* outp = g_v + ((size_t)b * DIM + cl) * NPIX + x0 + threadIdx.x;
#pragma unroll
    for (int half = 0; half < 2; half++) {
        const int ly = threadIdx.y + half * 8;
        float a = 0.f;
#pragma unroll
        for (int ky = 0; ky < 3; ky++)
#pragma unroll
            for (int kx = 0; kx < 3; kx++)
                a = fmaf(w[ky * 3 + kx], tile[ly + ky][threadIdx.x + kx], a);
        outp[(size_t)(y0 + ly) * WW] = a;
    }
}

// ---- kernel 4: normalize + triple top-k softmax + combine ------------------
__global__ void k_comb(const float* __restrict__ temp, const float* __restrict__ a1,
                       const float* __restrict__ a2, const float* __restrict__ a3) {
    const int bh = blockIdx.x;
    const int b = bh >> 1, h = bh & 1;
    const int i = threadIdx.x;

    __shared__ float nks[CH];
    float nq = fmaxf(sqrtf(g_sqn[b * 2 * DIM + h * CH + i]), 1e-12f);
    float nk = fmaxf(sqrtf(g_sqn[b * 2 * DIM + DIM + h * CH + i]), 1e-12f);
    nks[i] = nk;
    __syncthreads();

    const float t = temp[h];
    float v[CH];
#pragma unroll
    for (int j = 0; j < CH; j++)
        v[j] = g_gram[bh * CH * CH + i * CH + j] / nq * t / nks[j];

    int rank[CH];
#pragma unroll
    for (int j = 0; j < CH; j++) {
        int r = 0; float vj = v[j];
#pragma unroll
        for (int l = 0; l < CH; l++)
            r += (v[l] > vj) || (v[l] == vj && l < j);
        rank[j] = r;
    }
    float mx = -1e30f;
#pragma unroll
    for (int j = 0; j < CH; j++) mx = fmaxf(mx, v[j]);
    float e[CH], s16 = 0.f, s21 = 0.f, s24 = 0.f;
#pragma unroll
    for (int j = 0; j < CH; j++) {
        float ev = expf(v[j] - mx);
        e[j] = ev;
        if (rank[j] < 16) s16 += ev;
        if (rank[j] < 21) s21 += ev;
        if (rank[j] < 24) s24 += ev;
    }
    const float w1 = a1[0] / s16, w2 = a2[0] / s21, w3 = a3[0] / s24;
#pragma unroll
    for (int j = 0; j < CH; j++) {
        float coef = (rank[j] < 16 ? w1 : 0.f) + (rank[j] < 21 ? w2 : 0.f)
                   + (rank[j] < 24 ? w3 : 0.f);
        g_A[bh * CH * CH + i * CH + j] = e[j] * coef;
    }
}

// ---- kernel 5: M[b] = W_proj @ blockdiag(A) --------------------------------
__global__ void k_buildM(const float* __restrict__ wproj) {
    const int b = blockIdx.x;
    __shared__ float As[HEADS * CH * CH];
    __shared__ float Ws[DIM * DIM];
    const int tid = threadIdx.x;
    for (int idx = tid; idx < HEADS * CH * CH; idx += 128) As[idx] = g_A[b * HEADS * CH * CH + idx];
    for (int idx = tid; idx < DIM * DIM; idx += 128)       Ws[idx] = wproj[idx];
    __syncthreads();
#pragma unroll
    for (int m = 0; m < 32; m++) {
        int idx = tid + 128 * m;
        int o = idx >> 6, ci = idx & 63;
        int h = ci >> 5, cj = ci & 31;
        float s = 0.f;
#pragma unroll
        for (int cp = 0; cp < CH; cp++)
            s = fmaf(Ws[o * DIM + h * CH + cp], As[h * CH * CH + cp * CH + cj], s);
        g_M[b * DIM * DIM + idx] = s;
    }
}

// ---- kernel 6: out = M[b] @ v ----------------------------------------------
__global__ __launch_bounds__(256) void k_out(float* __restrict__ out) {
    extern __shared__ float sm[];
    float* ms = sm;             // [64][64] transposed M
    float* vs = sm + DIM * DIM; // [64][256]
    const int b = blockIdx.y;
    const long n0 = (long)blockIdx.x * 256;
    const int tx = threadIdx.x, ty = threadIdx.y;
    const int tid = ty * 16 + tx;

    const float* Mb = g_M + b * DIM * DIM;
    for (int idx = tid; idx < DIM * DIM; idx += 256) {
        int o = idx >> 6, ci = idx & 63;
        ms[ci * DIM + o] = Mb[idx];
    }
    const float* vg = g_v + (size_t)b * DIM * NPIX + n0;
    for (int idx = tid; idx < 64 * 64; idx += 256) {
        int ci = idx >> 6, pv = idx & 63;
        ((float4*)&vs[ci * 256])[pv] = ((const float4*)(vg + (size_t)ci * NPIX))[pv];
    }
    __syncthreads();

    u64 acc[4][8];
#pragma unroll
    for (int i = 0; i < 4; i++)
#pragma unroll
        for (int j = 0; j < 8; j++) acc[i][j] = 0ull;

    const int ob4 = ty * 4;
#pragma unroll 4
    for (int ci = 0; ci < 64; ci++) {
        float4 w = *(float4*)&ms[ci * DIM + ob4];
        u64 wd[4] = {pk2(w.x, w.x), pk2(w.y, w.y), pk2(w.z, w.z), pk2(w.w, w.w)};
        u64 xp[8];
#pragma unroll
        for (int j = 0; j < 8; j++)
            xp[j] = *(const u64*)&vs[ci * 256 + 2 * (tx + 16 * j)];
#pragma unroll
        for (int i = 0; i < 4; i++)
#pragma unroll
            for (int j = 0; j < 8; j++)
                fma2(acc[i][j], wd[i], xp[j], acc[i][j]);
    }

    float* ob = out + (size_t)b * DIM * NPIX + n0;
#pragma unroll
    for (int i = 0; i < 4; i++)
#pragma unroll
        for (int j = 0; j < 8; j++) {
            float2 r = upk2(acc[i][j]);
            *(float2*)&ob[(size_t)(ob4 + i) * NPIX + 2 * (tx + 16 * j)] = r;
        }
}

extern "C" void kernel_launch(void* const* d_in, const int* in_sizes, int n_in,
                              void* d_out, int out_size) {
    const float* x     = (const float*)d_in[0];
    const float* wqkv  = (const float*)d_in[1];
    const float* wdw   = (const float*)d_in[2];
    const float* wproj = (const float*)d_in[3];
    const float* temp  = (const float*)d_in[4];
    const float* a1    = (const float*)d_in[5];
    const float* a2    = (const float*)d_in[6];
    const float* a3    = (const float*)d_in[7];
    float* out = (float*)d_out;

    cudaFuncSetAttribute(k_conv1,  cudaFuncAttributeMaxDynamicSharedMemorySize, 81920);
    cudaFuncSetAttribute(k_dwgram, cudaFuncAttributeMaxDynamicSharedMemorySize, 153600);
    cudaFuncSetAttribute(k_out,    cudaFuncAttributeMaxDynamicSharedMemorySize, 81920);

    k_zero<<<64, 256>>>();
    k_conv1<<<dim3(512, 8), dim3(16, 16), 81920>>>(x, wqkv);
    k_dwgram<<<dim3(8, 32, 16), 256, 153600>>>(wdw);
    k_dwv<<<dim3(8, 16, B * 64), dim3(32, 8)>>>(wdw);
    k_comb<<<16, 32>>>(temp, a1, a2, a3);
    k_buildM<<<8, 128>>>(wproj);
    k_out<<<dim3(256, 8), dim3(16, 16), 81920>>>(out);
}

// round 5
// speedup vs baseline: 1.5815x; 1.5815x over previous
#include <cuda_runtime.h>
#include <math.h>

#define B      8
#define DIM    64
#define HEADS  2
#define CH     32
#define HH     256
#define WW     256
#define NPIX   65536
#define QKVC   192

typedef unsigned long long u64;
__device__ __forceinline__ void fma2(u64& d, u64 a, u64 b, u64 c) {
    asm("fma.rn.f32x2 %0,%1,%2,%3;" : "=l"(d) : "l"(a), "l"(b), "l"(c));
}
__device__ __forceinline__ u64 pk2(float lo, float hi) {
    u64 r; asm("mov.b64 %0,{%1,%2};" : "=l"(r) : "f"(lo), "f"(hi)); return r;
}
__device__ __forceinline__ float2 upk2(u64 v) {
    float2 r; asm("mov.b64 {%0,%1},%2;" : "=f"(r.x), "=f"(r.y) : "l"(v)); return r;
}

__device__ float g_mid[(size_t)B * QKVC * NPIX];
__device__ float g_qkv[(size_t)B * QKVC * NPIX];
__device__ float g_gram[B * HEADS * CH * CH];
__device__ float g_sqn[B * 2 * DIM];
__device__ float g_A[B * HEADS * CH * CH];
__device__ float g_M[B * DIM * DIM];

__global__ void k_zero() {
    int t = blockIdx.x * blockDim.x + threadIdx.x;
    if (t < B * HEADS * CH * CH) g_gram[t] = 0.f;
    if (t < B * 2 * DIM)         g_sqn[t]  = 0.f;
}

// ---- kernel 1: 1x1 conv. grid (512 px-tiles, B, 2 oc-halves) ---------------
// Block 16x16; thread: 6 oc (3 f32x2 pairs) x 8 px. smem 56KB -> 3 CTA/SM.
__global__ __launch_bounds__(256) void k_conv1(const float* __restrict__ x,
                                               const float* __restrict__ wqkv) {
    extern __shared__ float sm[];
    float* ws = sm;             // [64][96]  ws[k][oc']
    float* xs = sm + 64 * 96;   // [64][128] xs[ic][px]

    const int b  = blockIdx.y;
    const int z  = blockIdx.z;              // oc half
    const long n0 = (long)blockIdx.x * 128;
    const int tx = threadIdx.x, ty = threadIdx.y;
    const int tid = ty * 16 + tx;

    const float* wsrc = wqkv + z * 96 * 64;
    for (int idx = tid; idx < 96 * 64; idx += 256) {
        int oc = idx >> 6, k = idx & 63;
        ws[k * 96 + oc] = wsrc[idx];
    }
    const float* xb = x + (size_t)b * DIM * NPIX + n0;
    for (int idx = tid; idx < 64 * 32; idx += 256) {
        int ic = idx >> 5, pv = idx & 31;
        ((float4*)&xs[ic * 128])[pv] = ((const float4*)(xb + (size_t)ic * NPIX))[pv];
    }
    __syncthreads();

    u64 acc[3][8];
#pragma unroll
    for (int p = 0; p < 3; p++)
#pragma unroll
        for (int j = 0; j < 8; j++) acc[p][j] = 0ull;

    const int ocb = ty * 6;
#pragma unroll 4
    for (int k = 0; k < 64; k++) {
        const u64* wp = (const u64*)(ws + k * 96 + ocb);
        u64 wr0 = wp[0], wr1 = wp[1], wr2 = wp[2];
        u64 xd[8];
#pragma unroll
        for (int j = 0; j < 8; j++) {
            float xv = xs[k * 128 + tx + 16 * j];
            xd[j] = pk2(xv, xv);
        }
#pragma unroll
        for (int j = 0; j < 8; j++) {
            fma2(acc[0][j], wr0, xd[j], acc[0][j]);
            fma2(acc[1][j], wr1, xd[j], acc[1][j]);
            fma2(acc[2][j], wr2, xd[j], acc[2][j]);
        }
    }

    float* ob = g_mid + (size_t)b * QKVC * NPIX + (size_t)(z * 96) * NPIX + n0;
#pragma unroll
    for (int p = 0; p < 3; p++)
#pragma unroll
        for (int j = 0; j < 8; j++) {
            float2 r = upk2(acc[p][j]);
            ob[(size_t)(ocb + 2 * p) * NPIX + tx + 16 * j]     = r.x;
            ob[(size_t)(ocb + 2 * p + 1) * NPIX + tx + 16 * j] = r.y;
        }
}

// ---- kernel 2: depthwise 3x3 + fused sqn. 32x32 tile, 4 px/thread ----------
// block (8,32): thread (tx,ty) -> row ty, cols 4tx..4tx+3. Aligned float4 LDS.
__global__ void k_dw(const float* __restrict__ wdw) {
    const int bc = blockIdx.z;           // b*192 + c
    const int c  = bc % QKVC;
    const int b  = bc / QKVC;
    const int x0 = blockIdx.x * 32, y0 = blockIdx.y * 32;

    __shared__ float tile[34][36];       // rows gy-1.., cols gx-1..; pad to 36
    const float* in = g_mid + (size_t)bc * NPIX;
    const int tx = threadIdx.x, ty = threadIdx.y;
    const int tid = ty * 8 + tx;

    for (int idx = tid; idx < 34 * 34; idx += 256) {
        int yy = idx / 34, xx = idx % 34;
        int gy = y0 + yy - 1, gx = x0 + xx - 1;
        tile[yy][xx] = (gy >= 0 && gy < HH && gx >= 0 && gx < WW)
                           ? in[gy * WW + gx] : 0.f;
    }
    __syncthreads();

    float w[9];
#pragma unroll
    for (int t = 0; t < 9; t++) w[t] = wdw[c * 9 + t];

    float o0 = 0.f, o1 = 0.f, o2 = 0.f, o3 = 0.f;
#pragma unroll
    for (int ky = 0; ky < 3; ky++) {
        float4 lo = *(float4*)&tile[ty + ky][4 * tx];
        float4 hi = *(float4*)&tile[ty + ky][4 * tx + 4];
        float w0 = w[ky * 3], w1 = w[ky * 3 + 1], w2 = w[ky * 3 + 2];
        o0 = fmaf(w0, lo.x, fmaf(w1, lo.y, fmaf(w2, lo.z, o0)));
        o1 = fmaf(w0, lo.y, fmaf(w1, lo.z, fmaf(w2, lo.w, o1)));
        o2 = fmaf(w0, lo.z, fmaf(w1, lo.w, fmaf(w2, hi.x, o2)));
        o3 = fmaf(w0, lo.w, fmaf(w1, hi.x, fmaf(w2, hi.y, o3)));
    }
    float4 r = make_float4(o0, o1, o2, o3);
    *(float4*)&g_qkv[(size_t)bc * NPIX + (size_t)(y0 + ty) * WW + x0 + 4 * tx] = r;

    if (c < 2 * DIM) {
        float sq = fmaf(o0, o0, fmaf(o1, o1, fmaf(o2, o2, o3 * o3)));
#pragma unroll
        for (int o = 16; o; o >>= 1) sq += __shfl_down_sync(0xffffffffu, sq, o);
        __shared__ float red[8];
        if ((tid & 31) == 0) red[tid >> 5] = sq;
        __syncthreads();
        if (tid == 0) {
            float tot = 0.f;
#pragma unroll
            for (int wv = 0; wv < 8; wv++) tot += red[wv];
            atomicAdd(&g_sqn[b * 2 * DIM + c], tot);
        }
    }
}

// ---- kernel 3: Gram G = q@k^T. 4x4 interleaved f32x2 tile ------------------
// grid (64, 16), 256 thr = 4 groups x (8x8). Group g: px window 32g of stage.
__global__ __launch_bounds__(256) void k_gram() {
    __shared__ float qs[32][132];
    __shared__ float ks[32][132];

    const int bh = blockIdx.y;
    const int b = bh >> 1, h = bh & 1;
    const long n0 = (long)blockIdx.x * 1024;
    const float* qg = g_qkv + ((size_t)b * QKVC + h * CH) * NPIX + n0;
    const float* kg = g_qkv + ((size_t)b * QKVC + DIM + h * CH) * NPIX + n0;
    const int tid = threadIdx.x;
    const int g  = tid >> 6;
    const int gi = (tid >> 3) & 7;
    const int gj = tid & 7;

    u64 acc[4][4];
#pragma unroll
    for (int a = 0; a < 4; a++)
#pragma unroll
        for (int bb = 0; bb < 4; bb++) acc[a][bb] = 0ull;

    for (int s = 0; s < 8; s++) {
        __syncthreads();
        for (int idx = tid; idx < 1024; idx += 256) {
            int r = idx >> 5, pv = idx & 31;
            ((float4*)qs[r])[pv] = ((const float4*)(qg + (size_t)r * NPIX + s * 128))[pv];
            ((float4*)ks[r])[pv] = ((const float4*)(kg + (size_t)r * NPIX + s * 128))[pv];
        }
        __syncthreads();
#pragma unroll 4
        for (int p = g * 32; p < g * 32 + 32; p += 4) {
            ulonglong2 qa[4], kb[4];
#pragma unroll
            for (int a = 0; a < 4; a++) qa[a] = *(ulonglong2*)&qs[gi + 8 * a][p];
#pragma unroll
            for (int bb = 0; bb < 4; bb++) kb[bb] = *(ulonglong2*)&ks[gj + 8 * bb][p];
#pragma unroll
            for (int a = 0; a < 4; a++)
#pragma unroll
                for (int bb = 0; bb < 4; bb++) {
                    fma2(acc[a][bb], qa[a].x, kb[bb].x, acc[a][bb]);
                    fma2(acc[a][bb], qa[a].y, kb[bb].y, acc[a][bb]);
                }
        }
    }

    __syncthreads();
    float* red = &qs[0][0];   // 4224 floats >= 4096
#pragma unroll
    for (int a = 0; a < 4; a++)
#pragma unroll
        for (int bb = 0; bb < 4; bb++) {
            float2 r = upk2(acc[a][bb]);
            red[g * 1024 + (gi + 8 * a) * 32 + gj + 8 * bb] = r.x + r.y;
        }
    __syncthreads();
    for (int t = tid; t < 1024; t += 256) {
        float s = red[t] + red[1024 + t] + red[2048 + t] + red[3072 + t];
        atomicAdd(&g_gram[bh * 1024 + t], s);
    }
}

// ---- kernel 4: normalize + triple top-k softmax + combine ------------------
__global__ void k_comb(const float* __restrict__ temp, const float* __restrict__ a1,
                       const float* __restrict__ a2, const float* __restrict__ a3) {
    const int bh = blockIdx.x;
    const int b = bh >> 1, h = bh & 1;
    const int i = threadIdx.x;

    __shared__ float nks[CH];
    float nq = fmaxf(sqrtf(g_sqn[b * 2 * DIM + h * CH + i]), 1e-12f);
    float nk = fmaxf(sqrtf(g_sqn[b * 2 * DIM + DIM + h * CH + i]), 1e-12f);
    nks[i] = nk;
    __syncthreads();

    const float t = temp[h];
    float v[CH];
#pragma unroll
    for (int j = 0; j < CH; j++)
        v[j] = g_gram[bh * CH * CH + i * CH + j] / nq * t / nks[j];

    int rank[CH];
#pragma unroll
    for (int j = 0; j < CH; j++) {
        int r = 0; float vj = v[j];
#pragma unroll
        for (int l = 0; l < CH; l++)
            r += (v[l] > vj) || (v[l] == vj && l < j);
        rank[j] = r;
    }
    float mx = -1e30f;
#pragma unroll
    for (int j = 0; j < CH; j++) mx = fmaxf(mx, v[j]);
    float e[CH], s16 = 0.f, s21 = 0.f, s24 = 0.f;
#pragma unroll
    for (int j = 0; j < CH; j++) {
        float ev = expf(v[j] - mx);
        e[j] = ev;
        if (rank[j] < 16) s16 += ev;
        if (rank[j] < 21) s21 += ev;
        if (rank[j] < 24) s24 += ev;
    }
    const float w1 = a1[0] / s16, w2 = a2[0] / s21, w3 = a3[0] / s24;
#pragma unroll
    for (int j = 0; j < CH; j++) {
        float coef = (rank[j] < 16 ? w1 : 0.f) + (rank[j] < 21 ? w2 : 0.f)
                   + (rank[j] < 24 ? w3 : 0.f);
        g_A[bh * CH * CH + i * CH + j] = e[j] * coef;
    }
}

// ---- kernel 5: M[b] = W_proj @ blockdiag(A) --------------------------------
__global__ void k_buildM(const float* __restrict__ wproj) {
    const int b = blockIdx.x;
    __shared__ float As[HEADS * CH * CH];
    __shared__ float Ws[DIM * DIM];
    const int tid = threadIdx.x;
    for (int idx = tid; idx < HEADS * CH * CH; idx += 128) As[idx] = g_A[b * HEADS * CH * CH + idx];
    for (int idx = tid; idx < DIM * DIM; idx += 128)       Ws[idx] = wproj[idx];
    __syncthreads();
#pragma unroll
    for (int m = 0; m < 32; m++) {
        int idx = tid + 128 * m;
        int o = idx >> 6, ci = idx & 63;
        int h = ci >> 5, cj = ci & 31;
        float s = 0.f;
#pragma unroll
        for (int cp = 0; cp < CH; cp++)
            s = fmaf(Ws[o * DIM + h * CH + cp], As[h * CH * CH + cp * CH + cj], s);
        g_M[b * DIM * DIM + idx] = s;
    }
}

// ---- kernel 6: out = M[b] @ v ----------------------------------------------
__global__ __launch_bounds__(256) void k_out(float* __restrict__ out) {
    extern __shared__ float sm[];
    float* ms = sm;             // [64][64] transposed M
    float* vs = sm + DIM * DIM; // [64][256]
    const int b = blockIdx.y;
    const long n0 = (long)blockIdx.x * 256;
    const int tx = threadIdx.x, ty = threadIdx.y;
    const int tid = ty * 16 + tx;

    const float* Mb = g_M + b * DIM * DIM;
    for (int idx = tid; idx < DIM * DIM; idx += 256) {
        int o = idx >> 6, ci = idx & 63;
        ms[ci * DIM + o] = Mb[idx];
    }
    const float* vg = g_qkv + ((size_t)b * QKVC + 2 * DIM) * NPIX + n0;
    for (int idx = tid; idx < 64 * 64; idx += 256) {
        int ci = idx >> 6, pv = idx & 63;
        ((float4*)&vs[ci * 256])[pv] = ((const float4*)(vg + (size_t)ci * NPIX))[pv];
    }
    __syncthreads();

    u64 acc[4][8];
#pragma unroll
    for (int i = 0; i < 4; i++)
#pragma unroll
        for (int j = 0; j < 8; j++) acc[i][j] = 0ull;

    const int ob4 = ty * 4;
#pragma unroll 4
    for (int ci = 0; ci < 64; ci++) {
        float4 w = *(float4*)&ms[ci * DIM + ob4];
        u64 wd[4] = {pk2(w.x, w.x), pk2(w.y, w.y), pk2(w.z, w.z), pk2(w.w, w.w)};
        u64 xp[8];
#pragma unroll
        for (int j = 0; j < 8; j++)
            xp[j] = *(const u64*)&vs[ci * 256 + 2 * (tx + 16 * j)];
#pragma unroll
        for (int i = 0; i < 4; i++)
#pragma unroll
            for (int j = 0; j < 8; j++)
                fma2(acc[i][j], wd[i], xp[j], acc[i][j]);
    }

    float* ob = out + (size_t)b * DIM * NPIX + n0;
#pragma unroll
    for (int i = 0; i < 4; i++)
#pragma unroll
        for (int j = 0; j < 8; j++) {
            float2 r = upk2(acc[i][j]);
            *(float2*)&ob[(size_t)(ob4 + i) * NPIX + 2 * (tx + 16 * j)] = r;
        }
}

extern "C" void kernel_launch(void* const* d_in, const int* in_sizes, int n_in,
                              void* d_out, int out_size) {
    const float* x     = (const float*)d_in[0];
    const float* wqkv  = (const float*)d_in[1];
    const float* wdw   = (const float*)d_in[2];
    const float* wproj = (const float*)d_in[3];
    const float* temp  = (const float*)d_in[4];
    const float* a1    = (const float*)d_in[5];
    const float* a2    = (const float*)d_in[6];
    const float* a3    = (const float*)d_in[7];
    float* out = (float*)d_out;

    cudaFuncSetAttribute(k_conv1, cudaFuncAttributeMaxDynamicSharedMemorySize, 65536);
    cudaFuncSetAttribute(k_out,   cudaFuncAttributeMaxDynamicSharedMemorySize, 81920);

    k_zero<<<64, 256>>>();
    k_conv1<<<dim3(512, 8, 2), dim3(16, 16), 57344>>>(x, wqkv);
    k_dw<<<dim3(8, 8, B * QKVC), dim3(8, 32)>>>(wdw);
    k_gram<<<dim3(64, 16), 256>>>();
    k_comb<<<16, 32>>>(temp, a1, a2, a3);
    k_buildM<<<8, 128>>>(wproj);
    k_out<<<dim3(256, 8), dim3(16, 16), 81920>>>(out);
}